// round 6
// baseline (speedup 1.0000x reference)
#include <cuda_runtime.h>

#define B_ 256
#define S_ 197
#define D_ 768
#define D4_ 192
#define P_ 20
#define L_ 5
#define T_ 10
#define K_ 5
#define ROWS_TOK 75            // (T+K)*L
#define ROWS_ASSIST 50         // T*L
#define ROWS_SEL 25            // K*L
#define ROWS_PE 272            // ROWS_TOK + S
#define Q_ 8                   // mean/copy chunks per batch row
#define CHUNK 25               // rows per chunk (last chunk = 22)

// float offsets into d_out
#define PE_OFF   0ULL
#define SIM_OFF  53477376ULL
#define TOK_OFF  53477377ULL
#define IDX_OFF  68222977ULL
#define XN_OFF   68224257ULL

// scratch (device globals; no allocations)
__device__ float g_part[Q_ * B_ * D_];
__device__ float g_xnorm[B_ * D_];
__device__ float g_pnorm[P_ * D_];
__device__ int   g_idx[B_ * K_];
__device__ int   g_cnt[P_];

// 192-thread block reduce (padded to 256 in shared)
__device__ __forceinline__ float blk_reduce_192(float v) {
    __shared__ float sh[256];
    int t = threadIdx.x;
    sh[t] = v;
    if (t < 64) sh[192 + t] = 0.f;
    __syncthreads();
    for (int s = 128; s > 0; s >>= 1) {
        if (t < s) sh[t] += sh[t + s];
        __syncthreads();
    }
    return sh[0];
}

// ---------------------------------------------------------------------------
// Kernel 1: grid (B, Q_+3), block 192.
//  q<Q_   : stream x_embed rows chunk -> prompted_embedding[:, 75:, :] + partials
//  q==Q_  : b<P -> l2-normalize prompt_key row b; b==0 zeroes g_cnt + SIM
//  q>Q_   : 25 assist rows -> prompted_embedding[:, :50, :] AND tokens[:, :50, :]
// ---------------------------------------------------------------------------
__global__ void k_mean_copy(const float4* __restrict__ x,
                            const float4* __restrict__ pk,
                            const float4* __restrict__ assist,
                            float* __restrict__ out) {
    int b = blockIdx.x;
    int q = blockIdx.y;
    int t = threadIdx.x;                 // 0..191

    if (q == Q_) {
        if (b == 0 && t < P_) g_cnt[t] = 0;
        if (b == 0 && t == 0) out[SIM_OFF] = 0.f;
        if (b >= P_) return;
        float4 v = pk[(size_t)b * D4_ + t];
        float ss = blk_reduce_192(v.x * v.x + v.y * v.y + v.z * v.z + v.w * v.w);
        float r = rsqrtf(fmaxf(ss, 1e-12f));
        float4 n = make_float4(v.x * r, v.y * r, v.z * r, v.w * r);
        ((float4*)g_pnorm)[(size_t)b * D4_ + t] = n;
        return;
    }

    if (q > Q_) {
        // assist rows [r0, r0+25) for batch b -> both outputs
        int r0 = (q - Q_ - 1) * 25;
        float4* pe = (float4*)(out + PE_OFF) + (size_t)b * ROWS_PE * D4_ + t;
        float* tokbase = out + TOK_OFF + (size_t)b * ROWS_TOK * D_ + (size_t)t * 4;
#pragma unroll 5
        for (int i = 0; i < 25; i++) {
            int r = r0 + i;
            float4 v = assist[(size_t)r * D4_ + t];
            __stcs(pe + (size_t)r * D4_, v);
            float* to = tokbase + (size_t)r * D_;
            __stcs(to + 0, v.x);
            __stcs(to + 1, v.y);
            __stcs(to + 2, v.z);
            __stcs(to + 3, v.w);
        }
        return;
    }

    int s0 = q * CHUNK;
    int s1 = (q == Q_ - 1) ? S_ : s0 + CHUNK;

    const float4* xb = x + (size_t)b * S_ * D4_ + t;
    float4* ob = ((float4*)(out + PE_OFF)) + (size_t)b * ROWS_PE * D4_ + (size_t)ROWS_TOK * D4_ + t;

    float4 acc = make_float4(0.f, 0.f, 0.f, 0.f);
    int s = s0;
    for (; s + 5 <= s1; s += 5) {
        float4 v0 = __ldcs(xb + (size_t)(s + 0) * D4_);
        float4 v1 = __ldcs(xb + (size_t)(s + 1) * D4_);
        float4 v2 = __ldcs(xb + (size_t)(s + 2) * D4_);
        float4 v3 = __ldcs(xb + (size_t)(s + 3) * D4_);
        float4 v4 = __ldcs(xb + (size_t)(s + 4) * D4_);
        acc.x += v0.x + v1.x + v2.x + v3.x + v4.x;
        acc.y += v0.y + v1.y + v2.y + v3.y + v4.y;
        acc.z += v0.z + v1.z + v2.z + v3.z + v4.z;
        acc.w += v0.w + v1.w + v2.w + v3.w + v4.w;
        __stcs(ob + (size_t)(s + 0) * D4_, v0);
        __stcs(ob + (size_t)(s + 1) * D4_, v1);
        __stcs(ob + (size_t)(s + 2) * D4_, v2);
        __stcs(ob + (size_t)(s + 3) * D4_, v3);
        __stcs(ob + (size_t)(s + 4) * D4_, v4);
    }
    for (; s < s1; s++) {
        float4 v = __ldcs(xb + (size_t)s * D4_);
        acc.x += v.x; acc.y += v.y; acc.z += v.z; acc.w += v.w;
        __stcs(ob + (size_t)s * D4_, v);
    }
    ((float4*)g_part)[(size_t)q * B_ * D4_ + (size_t)b * D4_ + t] = acc;
}

// ---------------------------------------------------------------------------
// Kernel 2: grid B, block 192. Combine Q_ partials -> mean -> l2-normalize;
// write x_norm (out + scratch); 20 similarity dots; top-5 / idx / counts.
// ---------------------------------------------------------------------------
__global__ void k_xnorm_topk(float* __restrict__ out) {
    __shared__ float  sh[256];
    __shared__ float4 shx[D4_];
    __shared__ float  shsim[P_];
    int b = blockIdx.x;
    int t = threadIdx.x;

    const float4* part = (const float4*)g_part + (size_t)b * D4_ + t;
    float4 a = make_float4(0.f, 0.f, 0.f, 0.f);
#pragma unroll
    for (int q = 0; q < Q_; q++) {
        float4 c = part[(size_t)q * B_ * D4_];
        a.x += c.x; a.y += c.y; a.z += c.z; a.w += c.w;
    }
    const float inv = 1.0f / (float)S_;
    a.x *= inv; a.y *= inv; a.z *= inv; a.w *= inv;

    sh[t] = a.x * a.x + a.y * a.y + a.z * a.z + a.w * a.w;
    if (t < 64) sh[192 + t] = 0.f;
    __syncthreads();
    for (int s = 128; s > 0; s >>= 1) {
        if (t < s) sh[t] += sh[t + s];
        __syncthreads();
    }
    float r = rsqrtf(fmaxf(sh[0], 1e-12f));
    float4 n = make_float4(a.x * r, a.y * r, a.z * r, a.w * r);

    ((float4*)g_xnorm)[(size_t)b * D4_ + t] = n;
    float* xo = out + XN_OFF + (size_t)b * D_ + (size_t)t * 4;
    xo[0] = n.x; xo[1] = n.y; xo[2] = n.z; xo[3] = n.w;

    shx[t] = n;
    __syncthreads();

    int w = t >> 5;          // 0..5
    int lane = t & 31;
    for (int p = w; p < P_; p += 6) {
        const float4* pn = ((const float4*)g_pnorm) + (size_t)p * D4_;
        float acc = 0.f;
#pragma unroll
        for (int i = 0; i < 6; i++) {
            int j = lane + 32 * i;
            float4 pv = pn[j];
            float4 xv = shx[j];
            acc += xv.x * pv.x + xv.y * pv.y + xv.z * pv.z + xv.w * pv.w;
        }
#pragma unroll
        for (int off = 16; off > 0; off >>= 1)
            acc += __shfl_down_sync(0xffffffffu, acc, off);
        if (lane == 0) shsim[p] = acc;
    }
    __syncthreads();

    if (t == 0) {
        float sim[P_];
        bool used[P_];
#pragma unroll
        for (int p = 0; p < P_; p++) { sim[p] = shsim[p]; used[p] = false; }
        for (int k = 0; k < K_; k++) {
            float best = -3.4e38f;
            int bi = 0;
#pragma unroll
            for (int p = 0; p < P_; p++) {
                if (!used[p] && sim[p] > best) { best = sim[p]; bi = p; }
            }
            used[bi] = true;
            bool keep = best > 0.0f;
            int idxp = keep ? bi : -1;
            g_idx[b * K_ + k] = idxp;
            out[IDX_OFF + (size_t)b * K_ + k] = (float)idxp;
            if (keep) atomicAdd(&g_cnt[bi], 1);
        }
    }
}

// ---------------------------------------------------------------------------
// Kernel 3: grid (26, B), block 192.
//  r<25       : selected-prompt row -> prompted_embedding[:, 50+r, :] AND tokens.
//  r==25, b<4 : reduce_sim partial over 192 d's, atomicAdd into out[SIM_OFF].
// ---------------------------------------------------------------------------
__global__ void k_sel(const float4* __restrict__ prompt,
                      float* __restrict__ out) {
    int r = blockIdx.x;      // 0..25
    int b = blockIdx.y;
    int t = threadIdx.x;     // 0..191

    if (r == ROWS_SEL) {
        if (b >= 4) return;
        int d = b * 192 + t;
        // Sx[d] = sum_b x_norm[b][d] (coalesced over t); unroll x8 for MLP
        const float* xn = g_xnorm + d;
        float sx = 0.f;
#pragma unroll
        for (int bb = 0; bb < B_; bb += 8) {
            float v0 = xn[(size_t)(bb + 0) * D_];
            float v1 = xn[(size_t)(bb + 1) * D_];
            float v2 = xn[(size_t)(bb + 2) * D_];
            float v3 = xn[(size_t)(bb + 3) * D_];
            float v4 = xn[(size_t)(bb + 4) * D_];
            float v5 = xn[(size_t)(bb + 5) * D_];
            float v6 = xn[(size_t)(bb + 6) * D_];
            float v7 = xn[(size_t)(bb + 7) * D_];
            sx += ((v0 + v1) + (v2 + v3)) + ((v4 + v5) + (v6 + v7));
        }
        float kt = 0.f;
#pragma unroll
        for (int p = 0; p < P_; p++)
            kt += (float)g_cnt[p] * g_pnorm[(size_t)p * D_ + d];
        float tot = blk_reduce_192(sx * kt);
        if (t == 0) atomicAdd(out + SIM_OFF, tot * (1.0f / (float)B_));
        return;
    }

    int k = r / L_;
    int l = r % L_;
    int idx = g_idx[b * K_ + k];
    float4 v = make_float4(0.f, 0.f, 0.f, 0.f);
    if (idx >= 0)
        v = prompt[((size_t)idx * L_ + l) * D4_ + t];

    int row = ROWS_ASSIST + r;
    __stcs((float4*)(out + PE_OFF) + (size_t)b * ROWS_PE * D4_ + (size_t)row * D4_ + t, v);
    float* to = out + TOK_OFF + (size_t)b * ROWS_TOK * D_ + (size_t)row * D_ + (size_t)t * 4;
    __stcs(to + 0, v.x);
    __stcs(to + 1, v.y);
    __stcs(to + 2, v.z);
    __stcs(to + 3, v.w);
}

extern "C" void kernel_launch(void* const* d_in, const int* in_sizes, int n_in,
                              void* d_out, int out_size) {
    const float4* x_embed = (const float4*)d_in[0];        // [B,S,D]
    const float4* prompt = (const float4*)d_in[1];         // [P,L,D]
    const float4* prompt_key = (const float4*)d_in[2];     // [P,D]
    const float4* assist = (const float4*)d_in[3];         // [T,L,D]
    float* out = (float*)d_out;

    k_mean_copy<<<dim3(B_, Q_ + 3), D4_>>>(x_embed, prompt_key, assist, out);
    k_xnorm_topk<<<B_, D4_>>>(out);
    k_sel<<<dim3(ROWS_SEL + 1, B_), D4_>>>(prompt, out);
}

// round 7
// speedup vs baseline: 1.0361x; 1.0361x over previous
#include <cuda_runtime.h>

#define B_ 256
#define S_ 197
#define D_ 768
#define D4_ 192
#define P_ 20
#define L_ 5
#define T_ 10
#define K_ 5
#define ROWS_TOK 75            // (T+K)*L
#define ROWS_ASSIST 50         // T*L
#define ROWS_PE 272            // ROWS_TOK + S
#define Q_ 8                   // mean/copy chunks per batch row
#define CHUNK 25               // rows per chunk (last chunk = 22)
#define TGRP 15                // token rows per k3 block
#define NTG 5                  // token groups (5*15 = 75)
#define RSB 16                 // reduce_sim blocks (16 b's each)

// float offsets into d_out
#define PE_OFF   0ULL
#define SIM_OFF  53477376ULL
#define TOK_OFF  53477377ULL
#define IDX_OFF  68222977ULL
#define XN_OFF   68224257ULL

// scratch (device globals; no allocations)
__device__ float g_part[Q_ * B_ * D_];
__device__ float g_xnorm[B_ * D_];
__device__ float g_pnorm[P_ * D_];
__device__ int   g_idx[B_ * K_];
__device__ int   g_cnt[P_];

// 192-thread block reduce (padded to 256 in shared)
__device__ __forceinline__ float blk_reduce_192(float v) {
    __shared__ float sh[256];
    int t = threadIdx.x;
    sh[t] = v;
    if (t < 64) sh[192 + t] = 0.f;
    __syncthreads();
    for (int s = 128; s > 0; s >>= 1) {
        if (t < s) sh[t] += sh[t + s];
        __syncthreads();
    }
    return sh[0];
}

// ---------------------------------------------------------------------------
// Kernel 1: grid (B, Q_+1), block 192.
//  q<Q_ : stream x_embed rows chunk -> prompted_embedding[:, 75:, :] + partials.
//  q==Q_: b<P -> l2-normalize prompt_key row b; b==0 zeroes g_cnt + SIM slot.
// ---------------------------------------------------------------------------
__global__ void k_mean_copy(const float4* __restrict__ x,
                            const float4* __restrict__ pk,
                            float* __restrict__ out) {
    int b = blockIdx.x;
    int q = blockIdx.y;
    int t = threadIdx.x;                 // 0..191

    if (q == Q_) {
        if (b == 0 && t < P_) g_cnt[t] = 0;
        if (b == 0 && t == 0) out[SIM_OFF] = 0.f;
        if (b >= P_) return;
        float4 v = pk[(size_t)b * D4_ + t];
        float ss = blk_reduce_192(v.x * v.x + v.y * v.y + v.z * v.z + v.w * v.w);
        float r = rsqrtf(fmaxf(ss, 1e-12f));
        float4 n = make_float4(v.x * r, v.y * r, v.z * r, v.w * r);
        ((float4*)g_pnorm)[(size_t)b * D4_ + t] = n;
        return;
    }

    int s0 = q * CHUNK;
    int s1 = (q == Q_ - 1) ? S_ : s0 + CHUNK;

    const float4* xb = x + (size_t)b * S_ * D4_ + t;
    float4* ob = ((float4*)(out + PE_OFF)) + (size_t)b * ROWS_PE * D4_ + (size_t)ROWS_TOK * D4_ + t;

    float4 acc = make_float4(0.f, 0.f, 0.f, 0.f);
    int s = s0;
    for (; s + 5 <= s1; s += 5) {
        float4 v0 = __ldcs(xb + (size_t)(s + 0) * D4_);
        float4 v1 = __ldcs(xb + (size_t)(s + 1) * D4_);
        float4 v2 = __ldcs(xb + (size_t)(s + 2) * D4_);
        float4 v3 = __ldcs(xb + (size_t)(s + 3) * D4_);
        float4 v4 = __ldcs(xb + (size_t)(s + 4) * D4_);
        acc.x += v0.x + v1.x + v2.x + v3.x + v4.x;
        acc.y += v0.y + v1.y + v2.y + v3.y + v4.y;
        acc.z += v0.z + v1.z + v2.z + v3.z + v4.z;
        acc.w += v0.w + v1.w + v2.w + v3.w + v4.w;
        __stcs(ob + (size_t)(s + 0) * D4_, v0);
        __stcs(ob + (size_t)(s + 1) * D4_, v1);
        __stcs(ob + (size_t)(s + 2) * D4_, v2);
        __stcs(ob + (size_t)(s + 3) * D4_, v3);
        __stcs(ob + (size_t)(s + 4) * D4_, v4);
    }
    for (; s < s1; s++) {
        float4 v = __ldcs(xb + (size_t)s * D4_);
        acc.x += v.x; acc.y += v.y; acc.z += v.z; acc.w += v.w;
        __stcs(ob + (size_t)s * D4_, v);
    }
    ((float4*)g_part)[(size_t)q * B_ * D4_ + (size_t)b * D4_ + t] = acc;
}

// ---------------------------------------------------------------------------
// Kernel 2: grid B, block 192. Combine Q_ partials -> mean -> l2-normalize;
// write x_norm (out + scratch); 20 similarity dots; top-5 / idx / counts.
// ---------------------------------------------------------------------------
__global__ void k_xnorm_topk(float* __restrict__ out) {
    __shared__ float  sh[256];
    __shared__ float4 shx[D4_];
    __shared__ float  shsim[P_];
    int b = blockIdx.x;
    int t = threadIdx.x;

    const float4* part = (const float4*)g_part + (size_t)b * D4_ + t;
    float4 a = make_float4(0.f, 0.f, 0.f, 0.f);
#pragma unroll
    for (int q = 0; q < Q_; q++) {
        float4 c = part[(size_t)q * B_ * D4_];
        a.x += c.x; a.y += c.y; a.z += c.z; a.w += c.w;
    }
    const float inv = 1.0f / (float)S_;
    a.x *= inv; a.y *= inv; a.z *= inv; a.w *= inv;

    sh[t] = a.x * a.x + a.y * a.y + a.z * a.z + a.w * a.w;
    if (t < 64) sh[192 + t] = 0.f;
    __syncthreads();
    for (int s = 128; s > 0; s >>= 1) {
        if (t < s) sh[t] += sh[t + s];
        __syncthreads();
    }
    float r = rsqrtf(fmaxf(sh[0], 1e-12f));
    float4 n = make_float4(a.x * r, a.y * r, a.z * r, a.w * r);

    ((float4*)g_xnorm)[(size_t)b * D4_ + t] = n;
    float* xo = out + XN_OFF + (size_t)b * D_ + (size_t)t * 4;
    xo[0] = n.x; xo[1] = n.y; xo[2] = n.z; xo[3] = n.w;

    shx[t] = n;
    __syncthreads();

    int w = t >> 5;          // 0..5
    int lane = t & 31;
    for (int p = w; p < P_; p += 6) {
        const float4* pn = ((const float4*)g_pnorm) + (size_t)p * D4_;
        float acc = 0.f;
#pragma unroll
        for (int i = 0; i < 6; i++) {
            int j = lane + 32 * i;
            float4 pv = pn[j];
            float4 xv = shx[j];
            acc += xv.x * pv.x + xv.y * pv.y + xv.z * pv.z + xv.w * pv.w;
        }
#pragma unroll
        for (int off = 16; off > 0; off >>= 1)
            acc += __shfl_down_sync(0xffffffffu, acc, off);
        if (lane == 0) shsim[p] = acc;
    }
    __syncthreads();

    if (t == 0) {
        float sim[P_];
        bool used[P_];
#pragma unroll
        for (int p = 0; p < P_; p++) { sim[p] = shsim[p]; used[p] = false; }
        for (int k = 0; k < K_; k++) {
            float best = -3.4e38f;
            int bi = 0;
#pragma unroll
            for (int p = 0; p < P_; p++) {
                if (!used[p] && sim[p] > best) { best = sim[p]; bi = p; }
            }
            used[bi] = true;
            bool keep = best > 0.0f;
            int idxp = keep ? bi : -1;
            g_idx[b * K_ + k] = idxp;
            out[IDX_OFF + (size_t)b * K_ + k] = (float)idxp;
            if (keep) atomicAdd(&g_cnt[bi], 1);
        }
    }
}

// ---------------------------------------------------------------------------
// Kernel 3: grid (NTG+1, B), block 192.
//  g<NTG       : 15 token rows (assist or selected) -> prompted_embedding[:, :75, :]
//                AND tokens. Batched 5-row loads for MLP.
//  g==NTG,b<16 : reduce_sim partial over 16 batch rows, atomicAdd to SIM slot.
// ---------------------------------------------------------------------------
__global__ void k_tokens(const float4* __restrict__ prompt,
                         const float4* __restrict__ assist,
                         float* __restrict__ out) {
    int g = blockIdx.x;      // 0..NTG
    int b = blockIdx.y;
    int t = threadIdx.x;     // 0..191

    if (g == NTG) {
        if (b >= RSB) return;
        // partial reduce_sim over bb in [16b, 16b+16)
        const float4* xn = (const float4*)g_xnorm + (size_t)(b * 16) * D4_ + t;
        float4 sx = make_float4(0.f, 0.f, 0.f, 0.f);
#pragma unroll
        for (int i = 0; i < 16; i++) {
            float4 v = xn[(size_t)i * D4_];
            sx.x += v.x; sx.y += v.y; sx.z += v.z; sx.w += v.w;
        }
        float4 kt = make_float4(0.f, 0.f, 0.f, 0.f);
#pragma unroll
        for (int p = 0; p < P_; p++) {
            float c = (float)g_cnt[p];
            float4 v = ((const float4*)g_pnorm)[(size_t)p * D4_ + t];
            kt.x += c * v.x; kt.y += c * v.y; kt.z += c * v.z; kt.w += c * v.w;
        }
        float partial = sx.x * kt.x + sx.y * kt.y + sx.z * kt.z + sx.w * kt.w;
        float tot = blk_reduce_192(partial);
        if (t == 0) atomicAdd(out + SIM_OFF, tot * (1.0f / (float)B_));
        return;
    }

    float4* pe = (float4*)(out + PE_OFF) + (size_t)b * ROWS_PE * D4_ + t;
    float* tokbase = out + TOK_OFF + (size_t)b * ROWS_TOK * D_ + (size_t)t * 4;

#pragma unroll
    for (int batch = 0; batch < 3; batch++) {
        int rbase = g * TGRP + batch * 5;
        float4 v[5];
#pragma unroll
        for (int i = 0; i < 5; i++) {
            int r = rbase + i;
            if (r < ROWS_ASSIST) {
                v[i] = assist[(size_t)r * D4_ + t];
            } else {
                int rr = r - ROWS_ASSIST;
                int idx = g_idx[b * K_ + rr / L_];
                v[i] = make_float4(0.f, 0.f, 0.f, 0.f);
                if (idx >= 0)
                    v[i] = prompt[((size_t)idx * L_ + (rr % L_)) * D4_ + t];
            }
        }
#pragma unroll
        for (int i = 0; i < 5; i++)
            __stcs(pe + (size_t)(rbase + i) * D4_, v[i]);
#pragma unroll
        for (int i = 0; i < 5; i++) {
            float* to = tokbase + (size_t)(rbase + i) * D_;
            __stcs(to + 0, v[i].x);
            __stcs(to + 1, v[i].y);
            __stcs(to + 2, v[i].z);
            __stcs(to + 3, v[i].w);
        }
    }
}

extern "C" void kernel_launch(void* const* d_in, const int* in_sizes, int n_in,
                              void* d_out, int out_size) {
    const float4* x_embed = (const float4*)d_in[0];        // [B,S,D]
    const float4* prompt = (const float4*)d_in[1];         // [P,L,D]
    const float4* prompt_key = (const float4*)d_in[2];     // [P,D]
    const float4* assist = (const float4*)d_in[3];         // [T,L,D]
    float* out = (float*)d_out;

    k_mean_copy<<<dim3(B_, Q_ + 1), D4_>>>(x_embed, prompt_key, out);
    k_xnorm_topk<<<B_, D4_>>>(out);
    k_tokens<<<dim3(NTG + 1, B_), D4_>>>(prompt, assist, out);
}